// round 3
// baseline (speedup 1.0000x reference)
#include <cuda_runtime.h>

// 3x3 VALID conv, 8192x8192 fp32 input, 8190x8190 fp32 output, + scalar bias.
// HBM-bound streaming kernel: ~537MB min traffic -> ~77us floor at ~7TB/s.
// Register sliding-window: each thread produces 4 cols x RPT rows; input rows
// rotate through 3 register buffers (RPT+2 loads per RPT output rows).

#define IW 8192
#define IH 8192
#define OW 8190
#define OH 8190
#define RPT 16   // output rows per thread (18 row-loads / 16 rows = 1.125x amp)
#define TPB 128  // threads per block; each thread does 4 cols -> 512 cols/block

__global__ __launch_bounds__(TPB) void Conv2D_35210141892837_kernel(
    const float* __restrict__ x,
    const float* __restrict__ wgt,
    const float* __restrict__ bias,
    float* __restrict__ out)
{
    const int c  = (blockIdx.x * TPB + threadIdx.x) * 4;   // output col base
    const int r0 = blockIdx.y * RPT;                       // output row base
    if (c >= OW || r0 >= OH) return;

    const float w00 = wgt[0], w01 = wgt[1], w02 = wgt[2];
    const float w10 = wgt[3], w11 = wgt[4], w12 = wgt[5];
    const float w20 = wgt[6], w21 = wgt[7], w22 = wgt[8];
    const float bv  = bias[0];

    const bool col_full = (c + 8 <= IW);        // can read 8 floats at col c
    const bool row_full = (r0 + RPT <= OH);     // all RPT rows valid

    if (col_full) {
        // Three rotating 8-float row buffers in registers.
        float buf[3][8];

        // Preload input rows r0 and r0+1 (in-bounds: r0 <= OH-1 <= 8189).
        {
            const float* p0 = x + (size_t)r0 * IW + c;
            float4 a = *(const float4*)(p0);
            float4 b = *(const float4*)(p0 + 4);
            buf[0][0]=a.x; buf[0][1]=a.y; buf[0][2]=a.z; buf[0][3]=a.w;
            buf[0][4]=b.x; buf[0][5]=b.y; buf[0][6]=b.z; buf[0][7]=b.w;
            const float* p1 = p0 + IW;
            float4 a1 = *(const float4*)(p1);
            float4 b1 = *(const float4*)(p1 + 4);
            buf[1][0]=a1.x; buf[1][1]=a1.y; buf[1][2]=a1.z; buf[1][3]=a1.w;
            buf[1][4]=b1.x; buf[1][5]=b1.y; buf[1][6]=b1.z; buf[1][7]=b1.w;
        }

        if (row_full) {
            #pragma unroll
            for (int i = 0; i < RPT; i++) {
                const int r = r0 + i;
                // Load input row r+2 into the rotating slot (r+2 <= 8191).
                {
                    const float* p = x + (size_t)(r + 2) * IW + c;
                    float4 a = *(const float4*)(p);
                    float4 b = *(const float4*)(p + 4);
                    float* d = buf[(i + 2) % 3];
                    d[0]=a.x; d[1]=a.y; d[2]=a.z; d[3]=a.w;
                    d[4]=b.x; d[5]=b.y; d[6]=b.z; d[7]=b.w;
                }
                const float* t = buf[ i      % 3];
                const float* m = buf[(i + 1) % 3];
                const float* l = buf[(i + 2) % 3];

                float o0 = bv, o1 = bv, o2 = bv, o3 = bv;
                o0 = fmaf(w00, t[0], o0); o0 = fmaf(w01, t[1], o0); o0 = fmaf(w02, t[2], o0);
                o0 = fmaf(w10, m[0], o0); o0 = fmaf(w11, m[1], o0); o0 = fmaf(w12, m[2], o0);
                o0 = fmaf(w20, l[0], o0); o0 = fmaf(w21, l[1], o0); o0 = fmaf(w22, l[2], o0);
                o1 = fmaf(w00, t[1], o1); o1 = fmaf(w01, t[2], o1); o1 = fmaf(w02, t[3], o1);
                o1 = fmaf(w10, m[1], o1); o1 = fmaf(w11, m[2], o1); o1 = fmaf(w12, m[3], o1);
                o1 = fmaf(w20, l[1], o1); o1 = fmaf(w21, l[2], o1); o1 = fmaf(w22, l[3], o1);
                o2 = fmaf(w00, t[2], o2); o2 = fmaf(w01, t[3], o2); o2 = fmaf(w02, t[4], o2);
                o2 = fmaf(w10, m[2], o2); o2 = fmaf(w11, m[3], o2); o2 = fmaf(w12, m[4], o2);
                o2 = fmaf(w20, l[2], o2); o2 = fmaf(w21, l[3], o2); o2 = fmaf(w22, l[4], o2);
                o3 = fmaf(w00, t[3], o3); o3 = fmaf(w01, t[4], o3); o3 = fmaf(w02, t[5], o3);
                o3 = fmaf(w10, m[3], o3); o3 = fmaf(w11, m[4], o3); o3 = fmaf(w12, m[5], o3);
                o3 = fmaf(w20, l[3], o3); o3 = fmaf(w21, l[4], o3); o3 = fmaf(w22, l[5], o3);

                // Output row stride 8190 floats is only 8B-aligned -> float2 stores.
                float* po = out + (size_t)r * OW + c;
                *(float2*)(po)     = make_float2(o0, o1);
                *(float2*)(po + 2) = make_float2(o2, o3);
            }
        } else {
            // Last row-block: guard per row.
            #pragma unroll
            for (int i = 0; i < RPT; i++) {
                const int r = r0 + i;
                if (r >= OH) break;
                {
                    const float* p = x + (size_t)(r + 2) * IW + c;
                    float4 a = *(const float4*)(p);
                    float4 b = *(const float4*)(p + 4);
                    float* d = buf[(i + 2) % 3];
                    d[0]=a.x; d[1]=a.y; d[2]=a.z; d[3]=a.w;
                    d[4]=b.x; d[5]=b.y; d[6]=b.z; d[7]=b.w;
                }
                const float* t = buf[ i      % 3];
                const float* m = buf[(i + 1) % 3];
                const float* l = buf[(i + 2) % 3];
                float o[4];
                #pragma unroll
                for (int j = 0; j < 4; j++) {
                    float acc = bv;
                    acc = fmaf(w00, t[j],   acc); acc = fmaf(w01, t[j+1], acc); acc = fmaf(w02, t[j+2], acc);
                    acc = fmaf(w10, m[j],   acc); acc = fmaf(w11, m[j+1], acc); acc = fmaf(w12, m[j+2], acc);
                    acc = fmaf(w20, l[j],   acc); acc = fmaf(w21, l[j+1], acc); acc = fmaf(w22, l[j+2], acc);
                    o[j] = acc;
                }
                float* po = out + (size_t)r * OW + c;
                *(float2*)(po)     = make_float2(o[0], o[1]);
                *(float2*)(po + 2) = make_float2(o[2], o[3]);
            }
        }
    } else {
        // Column-boundary thread (c == 8188): scalar guarded path.
        for (int i = 0; i < RPT; i++) {
            const int r = r0 + i;
            if (r >= OH) break;
            #pragma unroll
            for (int j = 0; j < 4; j++) {
                const int col = c + j;
                if (col >= OW) break;
                const float* p0 = x + (size_t)r * IW + col;
                const float* p1 = p0 + IW;
                const float* p2 = p1 + IW;
                float acc = bv;
                acc = fmaf(w00, p0[0], acc); acc = fmaf(w01, p0[1], acc); acc = fmaf(w02, p0[2], acc);
                acc = fmaf(w10, p1[0], acc); acc = fmaf(w11, p1[1], acc); acc = fmaf(w12, p1[2], acc);
                acc = fmaf(w20, p2[0], acc); acc = fmaf(w21, p2[1], acc); acc = fmaf(w22, p2[2], acc);
                out[(size_t)r * OW + col] = acc;
            }
        }
    }
}

extern "C" void kernel_launch(void* const* d_in, const int* in_sizes, int n_in,
                              void* d_out, int out_size) {
    const float* x    = (const float*)d_in[0];
    const float* wgt  = (const float*)d_in[1];
    const float* bias = (const float*)d_in[2];
    float* out = (float*)d_out;

    dim3 block(TPB, 1, 1);
    dim3 grid((OW + TPB * 4 - 1) / (TPB * 4),   // 16
              (OH + RPT - 1) / RPT,             // 512
              1);
    Conv2D_35210141892837_kernel<<<grid, block>>>(x, wgt, bias, out);
}